// round 6
// baseline (speedup 1.0000x reference)
#include <cuda_runtime.h>
#include <cstdint>

// LGA: out[n,c,h,w] = sum_{i,j in 5x5} in1[n,c,h+i-2,w+j-2] * in2[n,i*5+j,h,w]
// Shapes fixed: in1 [4,32,384,768] f32, in2 [4,25,384,768] f32.
//
// Round-6: 4 output pixels per thread + packed fma.rn.f32x2.
//  - Per thread: 4 px -> window is 8 floats/row (32 B) instead of 2x6 floats
//    (48 B) -> LDS traffic drops 60 -> 40 B/output (L1 was the round-5 wall).
//  - 100 per-pixel taps held as 50 f32x2 register pairs; FFMA count halved
//    via fma.rn.f32x2 (bit-exact f32 FMA semantics).
//  - cp.async 4-stage smem ring over channels unchanged from round 5.

#define NDIM 4
#define CDIM 32
#define HDIM 384
#define WDIM 768
#define KTAPS 25
#define PLANE (HDIM * WDIM)

#define BX 16
#define BY 8
#define NTHR (BX * BY)                // 128
#define TILE_W 64                     // 16 threads * 4 px
#define TILE_H 8
#define SROWS (TILE_H + 4)            // 12
#define SPITCH 72                     // floats per smem row (288 B)
#define STAGE_ELEMS (SROWS * SPITCH)  // 864
#define STAGES 4
#define CHUNKS_PER_ROW 18             // 18 x 16B = 72 floats
#define NCHUNK (SROWS * CHUNKS_PER_ROW)  // 216 -> up to 2 chunks/thread

typedef unsigned long long u64;

__device__ __forceinline__ uint32_t smem_u32(const void* p) {
    return (uint32_t)__cvta_generic_to_shared(p);
}
__device__ __forceinline__ void cp_async16(uint32_t dst, const float* src, int sz) {
    asm volatile("cp.async.cg.shared.global [%0], [%1], 16, %2;\n"
                 :: "r"(dst), "l"(src), "r"(sz));
}
__device__ __forceinline__ void cp_commit() {
    asm volatile("cp.async.commit_group;\n" ::: "memory");
}
__device__ __forceinline__ void cp_wait2() {
    asm volatile("cp.async.wait_group 2;\n" ::: "memory");
}
__device__ __forceinline__ u64 pack2(float lo, float hi) {
    u64 r;
    asm("mov.b64 %0, {%1, %2};" : "=l"(r) : "f"(lo), "f"(hi));
    return r;
}
__device__ __forceinline__ void unpack2(u64 v, float& lo, float& hi) {
    asm("mov.b64 {%0, %1}, %2;" : "=f"(lo), "=f"(hi) : "l"(v));
}
__device__ __forceinline__ void fma2(u64& acc, u64 a, u64 b) {
    asm("fma.rn.f32x2 %0, %1, %2, %0;" : "+l"(acc) : "l"(a), "l"(b));
}

__global__ __launch_bounds__(NTHR, 3)
void lga_kernel(const float* __restrict__ in1,
                const float* __restrict__ in2,
                float* __restrict__ out) {
    __shared__ __align__(16) float ring[STAGES][STAGE_ELEMS];

    const int tx = threadIdx.x;            // 0..15
    const int ty = threadIdx.y;            // 0..7
    const int tid = ty * BX + tx;
    const int wbase = blockIdx.x * TILE_W;
    const int hbase = blockIdx.y * TILE_H;
    const int n = blockIdx.z;

    const int h = hbase + ty;              // output row
    const int w0 = wbase + 4 * tx;         // first of 4 output cols

    // ---- 25 per-pixel weight quads -> 50 packed f32x2 registers ----
    u64 w01[KTAPS], w23[KTAPS];
    {
        const float* wp = in2 + ((size_t)n * KTAPS * HDIM + h) * WDIM + w0;
#pragma unroll
        for (int t = 0; t < KTAPS; t++) {
            float4 v = __ldcs((const float4*)(wp + (size_t)t * PLANE));
            w01[t] = pack2(v.x, v.y);
            w23[t] = pack2(v.z, v.w);
        }
    }

    // ---- copy roles: up to 2 16B chunks per thread ----
    const float* in1n = in1 + (size_t)n * CDIM * PLANE;
    int  goff0 = 0, goff1 = 0, cpsz0 = 0, cpsz1 = 0, soff0 = 0, soff1 = 0;
    bool act1 = false;
    {
        // chunk 0: always active (tid < 128 <= NCHUNK)
        int k = tid;
        int r = k / CHUNKS_PER_ROW, ch = k - r * CHUNKS_PER_ROW;
        int gy = hbase - 2 + r, gx0 = wbase - 4 + 4 * ch;
        bool v = (gy >= 0) && (gy < HDIM) && (gx0 >= 0) && (gx0 + 3 < WDIM);
        goff0 = v ? (gy * WDIM + gx0) : 0;
        cpsz0 = v ? 16 : 0;
        soff0 = r * SPITCH + 4 * ch;
        // chunk 1
        k = tid + NTHR;
        act1 = (k < NCHUNK);
        r = k / CHUNKS_PER_ROW; ch = k - r * CHUNKS_PER_ROW;
        gy = hbase - 2 + r; gx0 = wbase - 4 + 4 * ch;
        v = act1 && (gy >= 0) && (gy < HDIM) && (gx0 >= 0) && (gx0 + 3 < WDIM);
        goff1 = v ? (gy * WDIM + gx0) : 0;
        cpsz1 = v ? 16 : 0;
        soff1 = r * SPITCH + 4 * ch;
    }

    float* po = out + (size_t)n * CDIM * PLANE + (size_t)h * WDIM + w0;

    uint32_t sdst0[STAGES], sdst1[STAGES];
#pragma unroll
    for (int s = 0; s < STAGES; s++) {
        sdst0[s] = smem_u32(&ring[s][soff0]);
        sdst1[s] = smem_u32(&ring[s][soff1]);
    }

    auto issue = [&](int c, int s) {
        const float* src = in1n + (size_t)c * PLANE;
        cp_async16(sdst0[s], src + goff0, cpsz0);
        if (act1) cp_async16(sdst1[s], src + goff1, cpsz1);
        cp_commit();
    };

    // ---- prologue: channels 0..2 in flight ----
    issue(0, 0);
    issue(1, 1);
    issue(2, 2);

#pragma unroll 1
    for (int c = 0; c < CDIM; c++) {
        const int s = c & (STAGES - 1);

        cp_wait2();          // group for channel c complete (>=2 still flying)
        __syncthreads();     // visibility + ring-reuse fence

        if (c + 3 < CDIM) issue(c + 3, (c + 3) & (STAGES - 1));
        else              cp_commit();   // keep wait-count math fixed

        // ---- compute 4 outputs of channel c ----
        // tile col of global col g is g-(wbase-4); window d0 = col w0-2 -> 4tx+2
        const float* basep = &ring[s][ty * SPITCH + 4 * tx + 2];
        u64 acc01 = 0, acc23 = 0;   // f32x2 (+0.0,+0.0)
#pragma unroll
        for (int i = 0; i < 5; i++) {
            const float* rp = basep + i * SPITCH;
            float2 A  = *(const float2*)(rp);       // d0 d1
            float4 Bq = *(const float4*)(rp + 2);   // d2..d5
            float2 C  = *(const float2*)(rp + 6);   // d6 d7

            u64 p01 = pack2(A.x, A.y);
            u64 p12 = pack2(A.y, Bq.x);
            u64 p23 = pack2(Bq.x, Bq.y);
            u64 p34 = pack2(Bq.y, Bq.z);
            u64 p45 = pack2(Bq.z, Bq.w);
            u64 p56 = pack2(Bq.w, C.x);
            u64 p67 = pack2(C.x, C.y);

            const u64* wr01 = &w01[5 * i];
            const u64* wr23 = &w23[5 * i];
            fma2(acc01, p01, wr01[0]);
            fma2(acc23, p23, wr23[0]);
            fma2(acc01, p12, wr01[1]);
            fma2(acc23, p34, wr23[1]);
            fma2(acc01, p23, wr01[2]);
            fma2(acc23, p45, wr23[2]);
            fma2(acc01, p34, wr01[3]);
            fma2(acc23, p56, wr23[3]);
            fma2(acc01, p45, wr01[4]);
            fma2(acc23, p67, wr23[4]);
        }
        float4 o;
        unpack2(acc01, o.x, o.y);
        unpack2(acc23, o.z, o.w);
        __stcs((float4*)(po + (size_t)c * PLANE), o);
    }
}

extern "C" void kernel_launch(void* const* d_in, const int* in_sizes, int n_in,
                              void* d_out, int out_size) {
    const float* in1 = (const float*)d_in[0];
    const float* in2 = (const float*)d_in[1];
    float* out = (float*)d_out;

    dim3 block(BX, BY);
    dim3 grid(WDIM / TILE_W, HDIM / TILE_H, NDIM);  // 12 x 48 x 4
    lga_kernel<<<grid, block>>>(in1, in2, out);
}

// round 7
// speedup vs baseline: 1.1250x; 1.1250x over previous
#include <cuda_runtime.h>
#include <cstdint>

// LGA: out[n,c,h,w] = sum_{i,j in 5x5} in1[n,c,h+i-2,w+j-2] * in2[n,i*5+j,h,w]
// Shapes fixed: in1 [4,32,384,768] f32, in2 [4,25,384,768] f32.
//
// Round-7: 4 px/thread + fma.rn.f32x2 (round-6 compute) with a 4-stage ring of
// CHANNEL PAIRS: one cp.async group / wait / __syncthreads per 2 channels.
// Halves the barrier count and doubles the independent work between syncs,
// which is what 12 warps/SM need to keep issue slots full.

#define NDIM 4
#define CDIM 32
#define HDIM 384
#define WDIM 768
#define KTAPS 25
#define PLANE (HDIM * WDIM)

#define BX 16
#define BY 8
#define NTHR (BX * BY)                // 128
#define TILE_W 64                     // 16 threads * 4 px
#define TILE_H 8
#define SROWS (TILE_H + 4)            // 12
#define SPITCH 72                     // floats per smem row (288 B)
#define STAGE_ELEMS (SROWS * SPITCH)  // 864 floats per channel
#define STAGES 4                      // ring of channel PAIRS
#define NPAIR (CDIM / 2)              // 16
#define CHUNKS_PER_ROW 18             // 18 x 16B = 72 floats
#define NCHUNK (SROWS * CHUNKS_PER_ROW)  // 216 chunks per channel

typedef unsigned long long u64;

__device__ __forceinline__ uint32_t smem_u32(const void* p) {
    return (uint32_t)__cvta_generic_to_shared(p);
}
__device__ __forceinline__ void cp_async16(uint32_t dst, const float* src, int sz) {
    asm volatile("cp.async.cg.shared.global [%0], [%1], 16, %2;\n"
                 :: "r"(dst), "l"(src), "r"(sz));
}
__device__ __forceinline__ void cp_commit() {
    asm volatile("cp.async.commit_group;\n" ::: "memory");
}
__device__ __forceinline__ void cp_wait2() {
    asm volatile("cp.async.wait_group 2;\n" ::: "memory");
}
__device__ __forceinline__ u64 pack2(float lo, float hi) {
    u64 r;
    asm("mov.b64 %0, {%1, %2};" : "=l"(r) : "f"(lo), "f"(hi));
    return r;
}
__device__ __forceinline__ void unpack2(u64 v, float& lo, float& hi) {
    asm("mov.b64 {%0, %1}, %2;" : "=f"(lo), "=f"(hi) : "l"(v));
}
__device__ __forceinline__ void fma2(u64& acc, u64 a, u64 b) {
    asm("fma.rn.f32x2 %0, %1, %2, %0;" : "+l"(acc) : "l"(a), "l"(b));
}

__global__ __launch_bounds__(NTHR, 3)
void lga_kernel(const float* __restrict__ in1,
                const float* __restrict__ in2,
                float* __restrict__ out) {
    // ring of channel pairs: [stage][channel-in-pair][elems]
    __shared__ __align__(16) float ring[STAGES][2][STAGE_ELEMS];

    const int tx = threadIdx.x;            // 0..15
    const int ty = threadIdx.y;            // 0..7
    const int tid = ty * BX + tx;
    const int wbase = blockIdx.x * TILE_W;
    const int hbase = blockIdx.y * TILE_H;
    const int n = blockIdx.z;

    const int h = hbase + ty;              // output row
    const int w0 = wbase + 4 * tx;         // first of 4 output cols

    // ---- 25 per-pixel weight quads -> 50 packed f32x2 registers ----
    u64 w01[KTAPS], w23[KTAPS];
    {
        const float* wp = in2 + ((size_t)n * KTAPS * HDIM + h) * WDIM + w0;
#pragma unroll
        for (int t = 0; t < KTAPS; t++) {
            float4 v = __ldcs((const float4*)(wp + (size_t)t * PLANE));
            w01[t] = pack2(v.x, v.y);
            w23[t] = pack2(v.z, v.w);
        }
    }

    // ---- copy roles: up to 2 16B chunks per thread per channel ----
    const float* in1n = in1 + (size_t)n * CDIM * PLANE;
    int  goff0 = 0, goff1 = 0, cpsz0 = 0, cpsz1 = 0, soff0 = 0, soff1 = 0;
    bool act1 = false;
    {
        int k = tid;                                  // chunk 0 (always active)
        int r = k / CHUNKS_PER_ROW, ch = k - r * CHUNKS_PER_ROW;
        int gy = hbase - 2 + r, gx0 = wbase - 4 + 4 * ch;
        bool v = (gy >= 0) && (gy < HDIM) && (gx0 >= 0) && (gx0 + 3 < WDIM);
        goff0 = v ? (gy * WDIM + gx0) : 0;
        cpsz0 = v ? 16 : 0;
        soff0 = r * SPITCH + 4 * ch;

        k = tid + NTHR;                               // chunk 1
        act1 = (k < NCHUNK);
        r = k / CHUNKS_PER_ROW; ch = k - r * CHUNKS_PER_ROW;
        gy = hbase - 2 + r; gx0 = wbase - 4 + 4 * ch;
        v = act1 && (gy >= 0) && (gy < HDIM) && (gx0 >= 0) && (gx0 + 3 < WDIM);
        goff1 = v ? (gy * WDIM + gx0) : 0;
        cpsz1 = v ? 16 : 0;
        soff1 = r * SPITCH + 4 * ch;
    }

    float* po = out + (size_t)n * CDIM * PLANE + (size_t)h * WDIM + w0;

    // issue the copy of channel pair p into stage s (one commit group)
    auto issue = [&](int p, int s) {
        const float* srcA = in1n + (size_t)(2 * p) * PLANE;
        const float* srcB = srcA + PLANE;
        uint32_t dA = smem_u32(&ring[s][0][0]);
        uint32_t dB = smem_u32(&ring[s][1][0]);
        cp_async16(dA + 4 * soff0, srcA + goff0, cpsz0);
        cp_async16(dB + 4 * soff0, srcB + goff0, cpsz0);
        if (act1) {
            cp_async16(dA + 4 * soff1, srcA + goff1, cpsz1);
            cp_async16(dB + 4 * soff1, srcB + goff1, cpsz1);
        }
        cp_commit();
    };

    // ---- prologue: pairs 0..2 (channels 0..5) in flight ----
    issue(0, 0);
    issue(1, 1);
    issue(2, 2);

#pragma unroll 1
    for (int p = 0; p < NPAIR; p++) {
        const int s = p & (STAGES - 1);

        cp_wait2();          // pair p complete (>=2 pairs still flying)
        __syncthreads();     // visibility + ring-reuse fence

        if (p + 3 < NPAIR) issue(p + 3, (p + 3) & (STAGES - 1));
        else               cp_commit();   // keep wait-count math fixed

        // ---- compute both channels of the pair (4 px each) ----
#pragma unroll
        for (int half = 0; half < 2; half++) {
            const float* basep = &ring[s][half][ty * SPITCH + 4 * tx + 2];
            u64 acc01 = 0, acc23 = 0;
#pragma unroll
            for (int i = 0; i < 5; i++) {
                const float* rp = basep + i * SPITCH;
                float2 A  = *(const float2*)(rp);       // d0 d1
                float4 Bq = *(const float4*)(rp + 2);   // d2..d5
                float2 C  = *(const float2*)(rp + 6);   // d6 d7

                u64 p01 = pack2(A.x, A.y);
                u64 p12 = pack2(A.y, Bq.x);
                u64 p23 = pack2(Bq.x, Bq.y);
                u64 p34 = pack2(Bq.y, Bq.z);
                u64 p45 = pack2(Bq.z, Bq.w);
                u64 p56 = pack2(Bq.w, C.x);
                u64 p67 = pack2(C.x, C.y);

                const u64* wr01 = &w01[5 * i];
                const u64* wr23 = &w23[5 * i];
                fma2(acc01, p01, wr01[0]);
                fma2(acc23, p23, wr23[0]);
                fma2(acc01, p12, wr01[1]);
                fma2(acc23, p34, wr23[1]);
                fma2(acc01, p23, wr01[2]);
                fma2(acc23, p45, wr23[2]);
                fma2(acc01, p34, wr01[3]);
                fma2(acc23, p56, wr23[3]);
                fma2(acc01, p45, wr01[4]);
                fma2(acc23, p67, wr23[4]);
            }
            float4 o;
            unpack2(acc01, o.x, o.y);
            unpack2(acc23, o.z, o.w);
            __stcs((float4*)(po + (size_t)(2 * p + half) * PLANE), o);
        }
    }
}

extern "C" void kernel_launch(void* const* d_in, const int* in_sizes, int n_in,
                              void* d_out, int out_size) {
    const float* in1 = (const float*)d_in[0];
    const float* in2 = (const float*)d_in[1];
    float* out = (float*)d_out;

    dim3 block(BX, BY);
    dim3 grid(WDIM / TILE_W, HDIM / TILE_H, NDIM);  // 12 x 48 x 4
    lga_kernel<<<grid, block>>>(in1, in2, out);
}